// round 1
// baseline (speedup 1.0000x reference)
#include <cuda_runtime.h>
#include <math.h>

#define N_PIX 4096
#define HW 64
#define THREADS 1024

__global__ void zero_kernel(float* out) { out[0] = 0.0f; }

__global__ __launch_bounds__(THREADS, 1)
void chamfer_kernel(const float* __restrict__ depth,
                    const float* __restrict__ bnd,
                    float* __restrict__ out,
                    float inv_total) {
    __shared__ float sg[N_PIX];
    __shared__ float sb[N_PIX];
    __shared__ float swarp[32];

    const int b   = blockIdx.x;
    const int tid = threadIdx.x;
    const float* d  = depth + b * N_PIX;
    const float* bb = bnd   + b * N_PIX;

    // ---- Phase 1: Sobel gradient magnitude into smem, copy boundary ----
    #pragma unroll
    for (int r = 0; r < N_PIX / THREADS; r++) {
        int i = tid + r * THREADS;
        int y = i >> 6, x = i & 63;
        float v[3][3];
        #pragma unroll
        for (int dy = -1; dy <= 1; dy++) {
            #pragma unroll
            for (int dx = -1; dx <= 1; dx++) {
                int yy = y + dy, xx = x + dx;
                bool ok = (yy >= 0) & (yy < HW) & (xx >= 0) & (xx < HW);
                v[dy + 1][dx + 1] = ok ? d[yy * HW + xx] : 0.0f;
            }
        }
        float gx = (v[0][0] - v[0][2]) + 2.0f * (v[1][0] - v[1][2]) + (v[2][0] - v[2][2]);
        float gy = (v[0][0] - v[2][0]) + 2.0f * (v[0][1] - v[2][1]) + (v[0][2] - v[2][2]);
        sg[i] = sqrtf(gx * gx + gy * gy + 1e-8f);
        sb[i] = bb[i];
    }
    __syncthreads();

    // ---- Phase 2: bitonic sort both arrays in-place (shared barriers) ----
    for (int k = 2; k <= N_PIX; k <<= 1) {
        for (int j = k >> 1; j > 0; j >>= 1) {
            #pragma unroll
            for (int r = 0; r < N_PIX / THREADS; r++) {
                int i = tid + r * THREADS;
                int p = i ^ j;
                if (p > i) {
                    bool up = ((i & k) == 0);
                    float a0 = sg[i], a1 = sg[p];
                    if ((a0 > a1) == up) { sg[i] = a1; sg[p] = a0; }
                    float c0 = sb[i], c1 = sb[p];
                    if ((c0 > c1) == up) { sb[i] = c1; sb[p] = c0; }
                }
            }
            __syncthreads();
        }
    }

    // ---- Phase 3: nearest-neighbor distances via binary search ----
    float acc = 0.0f;
    #pragma unroll
    for (int r = 0; r < N_PIX / THREADS; r++) {
        int i = tid + r * THREADS;

        // dist1: g_i -> nearest in sorted b
        {
            float x = sg[i];
            int lo = 0, hi = N_PIX;
            while (lo < hi) { int mid = (lo + hi) >> 1; if (sb[mid] < x) lo = mid + 1; else hi = mid; }
            float dmin = 3.4e38f;
            if (lo < N_PIX) dmin = sb[lo] - x;          // sb[lo] >= x, nonneg
            if (lo > 0)     dmin = fminf(dmin, x - sb[lo - 1]);
            acc += dmin;
        }
        // dist2: b_i -> nearest in sorted g
        {
            float x = sb[i];
            int lo = 0, hi = N_PIX;
            while (lo < hi) { int mid = (lo + hi) >> 1; if (sg[mid] < x) lo = mid + 1; else hi = mid; }
            float dmin = 3.4e38f;
            if (lo < N_PIX) dmin = sg[lo] - x;
            if (lo > 0)     dmin = fminf(dmin, x - sg[lo - 1]);
            acc += dmin;
        }
    }

    // ---- Phase 4: reduce and accumulate ----
    #pragma unroll
    for (int o = 16; o > 0; o >>= 1) acc += __shfl_xor_sync(0xffffffffu, acc, o);
    if ((tid & 31) == 0) swarp[tid >> 5] = acc;
    __syncthreads();
    if (tid < 32) {
        float v = swarp[tid];  // exactly 32 warps
        #pragma unroll
        for (int o = 16; o > 0; o >>= 1) v += __shfl_xor_sync(0xffffffffu, v, o);
        if (tid == 0) atomicAdd(out, v * inv_total);
    }
}

extern "C" void kernel_launch(void* const* d_in, const int* in_sizes, int n_in,
                              void* d_out, int out_size) {
    const float* depth = (const float*)d_in[0];
    const float* bnd   = (const float*)d_in[1];
    float* out = (float*)d_out;

    int B = in_sizes[0] / N_PIX;
    float inv_total = 1.0f / (float)(B * N_PIX);

    zero_kernel<<<1, 1>>>(out);
    chamfer_kernel<<<B, THREADS>>>(depth, bnd, out, inv_total);
}

// round 3
// speedup vs baseline: 2.6817x; 2.6817x over previous
#include <cuda_runtime.h>
#include <math.h>

#define HW 64
#define NP 4096          // elements per array (H*W)
#define MAXB 32

// scratch: [batch][arr(0=g,1=bnd)][4096]
__device__ __align__(16) float g_scr[2 * MAXB * NP];

__device__ __forceinline__ void ce_pair(float& a, float& b, bool dir) {
    float lo = fminf(a, b), hi = fmaxf(a, b);
    a = dir ? lo : hi;
    b = dir ? hi : lo;
}

// One bitonic phase (all j for given k) over 4*T elements.
// Thread t owns elements i = 4t..4t+3. Warp owns 128 contiguous elements.
// j>=128: smem exchange; 4<=j<=64: shfl; j=1,2: in-thread.
__device__ __forceinline__ void bitonic_phase(float v[4], float* sm, int t, int k, bool desc) {
    const int i0 = 4 * t;
    for (int j = k >> 1; j >= 128; j >>= 1) {
        __syncthreads();
        sm[i0 + 0] = v[0]; sm[i0 + 1] = v[1]; sm[i0 + 2] = v[2]; sm[i0 + 3] = v[3];
        __syncthreads();
        #pragma unroll
        for (int m = 0; m < 4; m++) {
            int i = i0 + m;
            float other = sm[i ^ j];
            bool lower = (i & j) == 0;
            bool dir = (((i & k) == 0) != desc);
            v[m] = (lower == dir) ? fminf(v[m], other) : fmaxf(v[m], other);
        }
    }
    int jstart = ((k >> 1) > 64) ? 64 : (k >> 1);
    for (int j = jstart; j >= 4; j >>= 1) {
        #pragma unroll
        for (int m = 0; m < 4; m++) {
            int i = i0 + m;
            float other = __shfl_xor_sync(0xffffffffu, v[m], j >> 2);
            bool lower = (i & j) == 0;
            bool dir = (((i & k) == 0) != desc);
            v[m] = (lower == dir) ? fminf(v[m], other) : fmaxf(v[m], other);
        }
    }
    if (k > 2) {  // j = 2 (same dir for both pairs since k >= 4)
        bool dir0 = (((i0 & k) == 0) != desc);
        ce_pair(v[0], v[2], dir0);
        ce_pair(v[1], v[3], dir0);
    }
    {   // j = 1 (dirs differ when k == 2)
        bool dirA = ((((i0 + 0) & k) == 0) != desc);
        bool dirB = ((((i0 + 2) & k) == 0) != desc);
        ce_pair(v[0], v[1], dirA);
        ce_pair(v[2], v[3], dirB);
    }
}

// K1: grid = B*2arrays*2chunks. Each block sorts one 2048-chunk (asc chunk0, desc chunk1).
__global__ __launch_bounds__(512, 2)
void sort_chunks_kernel(const float* __restrict__ depth,
                        const float* __restrict__ bnd,
                        float* __restrict__ out) {
    __shared__ float sm[2048];
    const int t = threadIdx.x;
    const int blk = blockIdx.x;
    const int c   = blk & 1;
    const int arr = (blk >> 1) & 1;
    const int b   = blk >> 2;
    const bool desc = (c == 1);

    if (blk == 0 && t == 0) out[0] = 0.0f;

    float v[4];
    const int e0 = c * 2048 + 4 * t;   // element index within the batch array
    if (arr == 1) {
        float4 q = *(const float4*)(bnd + b * NP + e0);
        v[0] = q.x; v[1] = q.y; v[2] = q.z; v[3] = q.w;
    } else {
        const float* d = depth + b * NP;
        #pragma unroll
        for (int m = 0; m < 4; m++) {
            int e = e0 + m;
            int y = e >> 6, x = e & 63;
            float p[3][3];
            #pragma unroll
            for (int dy = -1; dy <= 1; dy++)
                #pragma unroll
                for (int dx = -1; dx <= 1; dx++) {
                    int yy = y + dy, xx = x + dx;
                    bool ok = (yy >= 0) & (yy < HW) & (xx >= 0) & (xx < HW);
                    p[dy + 1][dx + 1] = ok ? d[yy * HW + xx] : 0.0f;
                }
            float gx = (p[0][0] - p[0][2]) + 2.0f * (p[1][0] - p[1][2]) + (p[2][0] - p[2][2]);
            float gy = (p[0][0] - p[2][0]) + 2.0f * (p[0][1] - p[2][1]) + (p[0][2] - p[2][2]);
            v[m] = sqrtf(gx * gx + gy * gy + 1e-8f);
        }
    }

    for (int k = 2; k <= 2048; k <<= 1)
        bitonic_phase(v, sm, t, k, desc);

    *(float4*)(g_scr + (b * 2 + arr) * NP + e0) = make_float4(v[0], v[1], v[2], v[3]);
}

// K2: grid = B*2. Final bitonic merge (k=4096) — asc/desc halves are already bitonic.
__global__ __launch_bounds__(1024, 1)
void merge_kernel() {
    __shared__ float sm[NP];
    const int t = threadIdx.x;
    float* base = g_scr + blockIdx.x * NP;
    float4 q = *(float4*)(base + 4 * t);
    float v[4] = {q.x, q.y, q.z, q.w};
    bitonic_phase(v, sm, t, NP, false);
    *(float4*)(base + 4 * t) = make_float4(v[0], v[1], v[2], v[3]);
}

// K3: grid = B*2 (batch, direction). Binary search each query against sorted target.
__global__ __launch_bounds__(1024, 1)
void query_kernel(float* __restrict__ out, float inv_total) {
    __shared__ float sT[NP];
    __shared__ float swarp[32];
    const int t = threadIdx.x;
    const int dir = blockIdx.x & 1;
    const int b   = blockIdx.x >> 1;

    const float* tgt = g_scr + (b * 2 + (dir == 0 ? 1 : 0)) * NP;
    const float* qry = g_scr + (b * 2 + (dir == 0 ? 0 : 1)) * NP;

    float4 tv = *(const float4*)(tgt + 4 * t);
    sT[4 * t + 0] = tv.x; sT[4 * t + 1] = tv.y; sT[4 * t + 2] = tv.z; sT[4 * t + 3] = tv.w;
    float4 qv = *(const float4*)(qry + 4 * t);
    float qs[4] = {qv.x, qv.y, qv.z, qv.w};
    __syncthreads();

    float acc = 0.0f;
    #pragma unroll
    for (int m = 0; m < 4; m++) {
        float x = qs[m];
        int pos = 0;                 // branchless lower_bound, saturates at NP-1
        #pragma unroll
        for (int s = 2048; s >= 1; s >>= 1) {
            if (sT[pos + s - 1] < x) pos += s;
        }
        // pos in [0, NP-1]. If x > all elements, pos = NP-1 and sT[pos] < x:
        // fabsf makes that candidate exactly the distance to the max element.
        float dmin = fabsf(sT[pos] - x);
        if (pos > 0) dmin = fminf(dmin, x - sT[pos - 1]);  // sT[pos-1] < x, nonneg
        acc += dmin;
    }

    #pragma unroll
    for (int o = 16; o > 0; o >>= 1) acc += __shfl_xor_sync(0xffffffffu, acc, o);
    if ((t & 31) == 0) swarp[t >> 5] = acc;
    __syncthreads();
    if (t < 32) {
        float z = swarp[t];   // exactly 32 warps
        #pragma unroll
        for (int o = 16; o > 0; o >>= 1) z += __shfl_xor_sync(0xffffffffu, z, o);
        if (t == 0) atomicAdd(out, z * inv_total);
    }
}

extern "C" void kernel_launch(void* const* d_in, const int* in_sizes, int n_in,
                              void* d_out, int out_size) {
    const float* depth = (const float*)d_in[0];
    const float* bnd   = (const float*)d_in[1];
    float* out = (float*)d_out;

    int B = in_sizes[0] / NP;
    if (B > MAXB) B = MAXB;
    float inv_total = 1.0f / (float)(B * NP);

    sort_chunks_kernel<<<B * 4, 512>>>(depth, bnd, out);
    merge_kernel<<<B * 2, 1024>>>();
    query_kernel<<<B * 2, 1024>>>(out, inv_total);
}

// round 4
// speedup vs baseline: 4.4450x; 1.6575x over previous
#include <cuda_runtime.h>
#include <math.h>

#define HW 64
#define NP 4096
#define CHUNK 2048
#define MAXB 32

// scratch: [batch][arr(0=g,1=bnd)][4096] — two sorted 2048-chunks per array
__device__ __align__(16) float g_scr[2 * MAXB * NP];

// K1: grid = B*4 (chunk, arr, batch). Each block sorts one ascending 2048-chunk.
// 1024 threads, 2 elements/thread. shfl for j=2..32, smem for j>=64.
__global__ __launch_bounds__(1024, 1)
void sort_kernel(const float* __restrict__ depth,
                 const float* __restrict__ bnd,
                 float* __restrict__ out) {
    __shared__ float sm[CHUNK];
    const int t   = threadIdx.x;
    const int blk = blockIdx.x;
    const int c   = blk & 1;
    const int arr = (blk >> 1) & 1;
    const int b   = blk >> 2;

    if (blk == 0 && t == 0) out[0] = 0.0f;

    const int i  = 2 * t;            // element index within chunk
    const int e0 = c * CHUNK + i;    // element index within the batch array

    float v0, v1;
    if (arr == 1) {
        float2 q = *(const float2*)(bnd + b * NP + e0);
        v0 = q.x; v1 = q.y;
    } else {
        const float* d = depth + b * NP;
        #pragma unroll
        for (int m = 0; m < 2; m++) {
            int e = e0 + m;
            int y = e >> 6, x = e & 63;
            float p[3][3];
            #pragma unroll
            for (int dy = -1; dy <= 1; dy++)
                #pragma unroll
                for (int dx = -1; dx <= 1; dx++) {
                    int yy = y + dy, xx = x + dx;
                    bool ok = (yy >= 0) & (yy < HW) & (xx >= 0) & (xx < HW);
                    p[dy + 1][dx + 1] = ok ? d[yy * HW + xx] : 0.0f;
                }
            float gx = (p[0][0] - p[0][2]) + 2.0f * (p[1][0] - p[1][2]) + (p[2][0] - p[2][2]);
            float gy = (p[0][0] - p[2][0]) + 2.0f * (p[0][1] - p[2][1]) + (p[0][2] - p[2][2]);
            float g = sqrtf(gx * gx + gy * gy + 1e-8f);
            if (m == 0) v0 = g; else v1 = g;
        }
    }

    // Bitonic sort, ascending. Element i = 2t+m; for j>=2 both elements share
    // the same partner thread (t ^ (j>>1)) and the same keepMin predicate.
    #pragma unroll
    for (int k = 2; k <= CHUNK; k <<= 1) {
        #pragma unroll
        for (int j = k >> 1; j >= 1; j >>= 1) {
            if (j >= 64) {
                __syncthreads();
                *(float2*)&sm[i] = make_float2(v0, v1);
                __syncthreads();
                bool keepMin = ((i & j) == 0) == ((i & k) == 0);
                float2 o = *(float2*)&sm[i ^ j];   // i even, j even -> aligned
                v0 = keepMin ? fminf(v0, o.x) : fmaxf(v0, o.x);
                v1 = keepMin ? fminf(v1, o.y) : fmaxf(v1, o.y);
            } else if (j >= 2) {
                bool keepMin = ((i & j) == 0) == ((i & k) == 0);
                float o0 = __shfl_xor_sync(0xffffffffu, v0, j >> 1);
                float o1 = __shfl_xor_sync(0xffffffffu, v1, j >> 1);
                v0 = keepMin ? fminf(v0, o0) : fmaxf(v0, o0);
                v1 = keepMin ? fminf(v1, o1) : fmaxf(v1, o1);
            } else {
                bool up = ((i & k) == 0);
                float lo = fminf(v0, v1), hi = fmaxf(v0, v1);
                v0 = up ? lo : hi;
                v1 = up ? hi : lo;
            }
        }
    }

    *(float2*)(g_scr + (b * 2 + arr) * NP + e0) = make_float2(v0, v1);
}

// K2: grid = B*4 (queryhalf, dir, batch). Target = both sorted chunks of the
// other array in smem; each query = min over two 11-deep lower_bounds.
__global__ __launch_bounds__(1024, 1)
void query_kernel(float* __restrict__ out, float inv_total) {
    __shared__ float sT[NP];
    __shared__ float swarp[32];
    const int t   = threadIdx.x;
    const int blk = blockIdx.x;
    const int h   = blk & 1;          // which half of the queries
    const int dir = (blk >> 1) & 1;   // 0: g->b, 1: b->g
    const int b   = blk >> 2;

    const float* tgt = g_scr + (b * 2 + (dir ^ 1)) * NP;
    const float* qry = g_scr + (b * 2 + dir) * NP;

    ((float4*)sT)[t] = ((const float4*)tgt)[t];          // 4096 floats
    float2 q = ((const float2*)(qry + h * CHUNK))[t];    // 2 queries/thread
    __syncthreads();

    float acc = 0.0f;
    #pragma unroll
    for (int m = 0; m < 2; m++) {
        float x = m ? q.y : q.x;
        float dmin = 3.4e38f;
        #pragma unroll
        for (int ch = 0; ch < 2; ch++) {
            const float* T = sT + ch * CHUNK;
            int pos = 0;                      // branchless lower_bound, saturates at CHUNK-1
            #pragma unroll
            for (int s = CHUNK / 2; s >= 1; s >>= 1) {
                if (T[pos + s - 1] < x) pos += s;
            }
            // If x > all elements: pos=CHUNK-1 and T[pos]<x; fabsf gives the
            // exact distance to the chunk max. Otherwise T[pos] >= x.
            float d = fabsf(T[pos] - x);
            if (pos > 0) d = fminf(d, x - T[pos - 1]);
            dmin = fminf(dmin, d);
        }
        acc += dmin;
    }

    #pragma unroll
    for (int o = 16; o > 0; o >>= 1) acc += __shfl_xor_sync(0xffffffffu, acc, o);
    if ((t & 31) == 0) swarp[t >> 5] = acc;
    __syncthreads();
    if (t < 32) {
        float z = swarp[t];   // exactly 32 warps
        #pragma unroll
        for (int o = 16; o > 0; o >>= 1) z += __shfl_xor_sync(0xffffffffu, z, o);
        if (t == 0) atomicAdd(out, z * inv_total);
    }
}

extern "C" void kernel_launch(void* const* d_in, const int* in_sizes, int n_in,
                              void* d_out, int out_size) {
    const float* depth = (const float*)d_in[0];
    const float* bnd   = (const float*)d_in[1];
    float* out = (float*)d_out;

    int B = in_sizes[0] / NP;
    if (B > MAXB) B = MAXB;
    float inv_total = 1.0f / (float)(B * NP);

    sort_kernel<<<B * 4, 1024>>>(depth, bnd, out);
    query_kernel<<<B * 4, 1024>>>(out, inv_total);
}